// round 4
// baseline (speedup 1.0000x reference)
#include <cuda_runtime.h>
#include <math.h>

// ---------------- problem dims ----------------
#define TT    10
#define BBs   4
#define CCh   256
#define NP    256          // H*W = 16*16
#define TRR   40           // STEP*RATIO
#define HIDD  1024
#define EPSL  1e-5f

#define BCN   (BBs*CCh*NP)     // 262144  (one time-step of (B,C,N))
#define BHN   (BBs*HIDD*NP)    // 1048576 (one time-step of (B,HID,N))
#define S_TBCN  (TT*BCN)       // 2,621,440
#define S_TRBCN (TRR*BBs*CCh*NP) // 10,485,760

// ---------------- scratch ----------------
__device__ float g_bufA[S_TRBCN];   // conv1 out (u,b,c,n) / fc1 out (t,b,o,n)
__device__ float g_bufB[S_TRBCN];   // lif1 spikes / fc1 spikes
__device__ float g_y[S_TBCN];       // generic (t,b,c,n) staging
__device__ float g_qs[S_TBCN];
__device__ float g_ks[S_TBCN];
__device__ float g_vs[S_TBCN];
__device__ float g_o[S_TBCN];
__device__ float g_h[S_TBCN];
__device__ float g_ktv[TT*BBs*16*256];   // (t,b,h)[16][16]
__device__ float g_scale[HIDD];
__device__ float g_shift[HIDD];
__device__ float g_t1s[TRR], g_t1h[TRR];
__device__ float g_t2s[TT],  g_t2h[TT];

// ---------------- BN folding: scale = g/sqrt(v+eps); shift = beta - m*scale (+ bias*scale) ----
__global__ void prep_bn_kernel(const float* __restrict__ bnp, const float* __restrict__ bias,
                               float* __restrict__ scale, float* __restrict__ shift, int cnum)
{
    int i = blockIdx.x * blockDim.x + threadIdx.x;
    if (i >= cnum) return;
    float g  = bnp[i];
    float be = bnp[cnum + i];
    float m  = bnp[2*cnum + i];
    float v  = bnp[3*cnum + i];
    float s  = g / sqrtf(v + EPSL);
    float sh = be - m * s;
    if (bias) sh += bias[i] * s;
    scale[i] = s;
    shift[i] = sh;
}

// ---------------- batched GEMM + BN epilogue ----------------
// Out[batch, o, n] = (sum_k W[o,k] * In[batch,k,n]) * scale[o] + shift[o]
// N fixed = 256.  Tile 64x64, BK=16, 256 threads, 4x4 micro-tile.
__global__ void gemm_bn_kernel(const float* __restrict__ In, const float* __restrict__ Wm,
                               float* __restrict__ Out, int O, int K,
                               const float* __restrict__ scale, const float* __restrict__ shift)
{
    __shared__ float sA[16][64];   // [k][o]
    __shared__ float sB[16][64];   // [k][n]
    int batch = blockIdx.z;
    int oBase = blockIdx.y * 64;
    int nBase = blockIdx.x * 64;
    const float* Bp = In + (size_t)batch * K * NP;
    float* Cp = Out + (size_t)batch * O * NP;
    int tid = threadIdx.x;
    int tx = tid & 15, ty = tid >> 4;
    int aoo = tid >> 2, ak4 = (tid & 3) << 2;
    int bkk = tid >> 4, bn4 = (tid & 15) << 2;

    float acc[4][4];
#pragma unroll
    for (int i = 0; i < 4; i++)
#pragma unroll
        for (int j = 0; j < 4; j++) acc[i][j] = 0.f;

    for (int k0 = 0; k0 < K; k0 += 16) {
        float4 av = *(const float4*)&Wm[(size_t)(oBase + aoo) * K + k0 + ak4];
        float4 bv = *(const float4*)&Bp[(size_t)(k0 + bkk) * NP + nBase + bn4];
        sA[ak4 + 0][aoo] = av.x; sA[ak4 + 1][aoo] = av.y;
        sA[ak4 + 2][aoo] = av.z; sA[ak4 + 3][aoo] = av.w;
        *(float4*)&sB[bkk][bn4] = bv;
        __syncthreads();
#pragma unroll
        for (int kk = 0; kk < 16; kk++) {
            float4 a = *(const float4*)&sA[kk][ty << 2];
            float4 b = *(const float4*)&sB[kk][tx << 2];
            acc[0][0] += a.x * b.x; acc[0][1] += a.x * b.y; acc[0][2] += a.x * b.z; acc[0][3] += a.x * b.w;
            acc[1][0] += a.y * b.x; acc[1][1] += a.y * b.y; acc[1][2] += a.y * b.z; acc[1][3] += a.y * b.w;
            acc[2][0] += a.z * b.x; acc[2][1] += a.z * b.y; acc[2][2] += a.z * b.z; acc[2][3] += a.z * b.w;
            acc[3][0] += a.w * b.x; acc[3][1] += a.w * b.y; acc[3][2] += a.w * b.z; acc[3][3] += a.w * b.w;
        }
        __syncthreads();
    }
#pragma unroll
    for (int i = 0; i < 4; i++) {
        int o = oBase + (ty << 2) + i;
        float sc = scale[o], sh = shift[o];
        float4 r;
        r.x = acc[i][0] * sc + sh; r.y = acc[i][1] * sc + sh;
        r.z = acc[i][2] * sc + sh; r.w = acc[i][3] * sc + sh;
        *(float4*)&Cp[(size_t)o * NP + nBase + (tx << 2)] = r;
    }
}

// ---------------- TIM conv1: (B,T=10 in-ch,C,H,W) -> (TR=40 out-ch), 3x3x3 over (C,H,W), pad 1, + BN(u)
// in  : (T,B,C,N) layout (logical NCDHW with batch b, channel t)
// out : (u,b,c,n)
#define CONV1_SMEM ((10800 + 10*3*18*19) * 4)
__global__ void tim_conv1_kernel(const float* __restrict__ in, const float* __restrict__ wup,
                                 const float* __restrict__ sc, const float* __restrict__ sh,
                                 float* __restrict__ out)
{
    extern __shared__ float smem[];
    float* sW  = smem;            // [270][40]  (u fastest for float4)
    float* sIn = smem + 10800;    // [t][dc][18][pitch 19]
    int c = blockIdx.x;
    int b = blockIdx.y;
    int tid = threadIdx.x;

    for (int i = tid; i < 10800; i += 256) {
        int u = i / 270, k = i % 270;
        sW[k * 40 + u] = wup[u * 270 + k];
    }
    for (int i = tid; i < 10 * 3 * 18 * 18; i += 256) {
        int ww = i % 18; int tmp = i / 18;
        int hh = tmp % 18; tmp /= 18;
        int dc = tmp % 3;  int t = tmp / 3;
        int ci = c + dc - 1;
        int hy = hh - 1, wx = ww - 1;
        float v = 0.f;
        if (ci >= 0 && ci < CCh && hy >= 0 && hy < 16 && wx >= 0 && wx < 16)
            v = in[(((size_t)t * BBs + b) * CCh + ci) * NP + hy * 16 + wx];
        sIn[((t * 3 + dc) * 18 + hh) * 19 + ww] = v;
    }
    __syncthreads();

    int h = tid >> 4, w = tid & 15;
    float acc[40];
#pragma unroll
    for (int u = 0; u < 40; u++) acc[u] = 0.f;

#pragma unroll 1
    for (int t = 0; t < 10; t++) {
#pragma unroll
        for (int dc = 0; dc < 3; dc++) {
#pragma unroll
            for (int dh = 0; dh < 3; dh++) {
                const float* rowp = &sIn[((t * 3 + dc) * 18 + h + dh) * 19 + w];
                const float4* wbase = (const float4*)&sW[((t * 3 + dc) * 3 + dh) * 3 * 40];
#pragma unroll
                for (int dw = 0; dw < 3; dw++) {
                    float v = rowp[dw];
                    const float4* wp = wbase + dw * 10;
#pragma unroll
                    for (int uq = 0; uq < 10; uq++) {
                        float4 w4 = wp[uq];
                        acc[uq * 4 + 0] += v * w4.x;
                        acc[uq * 4 + 1] += v * w4.y;
                        acc[uq * 4 + 2] += v * w4.z;
                        acc[uq * 4 + 3] += v * w4.w;
                    }
                }
            }
        }
    }
#pragma unroll
    for (int u = 0; u < 40; u++) {
        out[(((size_t)u * BBs + b) * CCh + c) * NP + tid] = acc[u] * sc[u] + sh[u];
    }
}

// ---------------- TIM conv2: grouped (groups=10), in (u,b,c,n) spikes -> out (t,b,c,n) + BN(t)
__global__ void tim_conv2_kernel(const float* __restrict__ sp, const float* __restrict__ wdn,
                                 const float* __restrict__ sc, const float* __restrict__ sh,
                                 float* __restrict__ out)
{
    __shared__ float sW[1080];
    int c = blockIdx.x;
    int t = blockIdx.y;
    int b = blockIdx.z;
    int tid = threadIdx.x;
    for (int i = tid; i < 1080; i += 256) sW[i] = wdn[i];
    __syncthreads();

    int h = tid >> 4, w = tid & 15;
    float acc = 0.f;
#pragma unroll
    for (int r = 0; r < 4; r++) {
        int u = t * 4 + r;
#pragma unroll
        for (int dc = 0; dc < 3; dc++) {
            int ci = c + dc - 1;
            if (ci < 0 || ci >= CCh) continue;
            const float* base = &sp[(((size_t)u * BBs + b) * CCh + ci) * NP];
            const float* wr = &sW[u * 27 + dc * 9];
#pragma unroll
            for (int dh = 0; dh < 3; dh++) {
                int hy = h + dh - 1;
                if (hy < 0 || hy >= 16) continue;
#pragma unroll
                for (int dw = 0; dw < 3; dw++) {
                    int wx = w + dw - 1;
                    if (wx < 0 || wx >= 16) continue;
                    acc += base[hy * 16 + wx] * wr[dh * 3 + dw];
                }
            }
        }
    }
    out[(((size_t)t * BBs + b) * CCh + c) * NP + tid] = acc * sc[t] + sh[t];
}

// ---------------- LIF: 10-step scan over stride; spikes out ----------------
__global__ void lif_kernel(const float* __restrict__ in, float* __restrict__ out,
                           int nChains, int stride, float vth)
{
    int i = blockIdx.x * blockDim.x + threadIdx.x;
    if (i >= nChains) return;
    float mem = 0.f;
    int p = i;
#pragma unroll
    for (int s = 0; s < 10; s++, p += stride) {
        float x = in[p];
        mem = mem + (x - mem) * 0.5f;
        float spk = ((mem - vth) > 0.f) ? 1.f : 0.f;
        out[p] = spk;
        if (spk != 0.f) mem = 0.f;
    }
}

__global__ void lif_resid_kernel(const float* __restrict__ in, const float* __restrict__ res,
                                 float* __restrict__ out, int nChains, int stride, float vth)
{
    int i = blockIdx.x * blockDim.x + threadIdx.x;
    if (i >= nChains) return;
    float mem = 0.f;
    int p = i;
#pragma unroll
    for (int s = 0; s < 10; s++, p += stride) {
        float x = in[p];
        mem = mem + (x - mem) * 0.5f;
        float spk = ((mem - vth) > 0.f) ? 1.f : 0.f;
        out[p] = res[p] + spk;
        if (spk != 0.f) mem = 0.f;
    }
}

// ---------------- KtV: per (t,b,head): Gram 16x16 = K_spike(16xN) . V_spike(16xN)^T over N ----
__global__ void ktv_kernel(const float* __restrict__ ks, const float* __restrict__ vs,
                           float* __restrict__ ktv)
{
    __shared__ float kT[16 * 257];
    __shared__ float vT[16 * 257];
    int tbh = blockIdx.x;            // (t*B + b)*16 + head
    int hh = tbh & 15;
    int tb = tbh >> 4;
    size_t base = ((size_t)tb * CCh + hh * 16) * NP;
    int tid = threadIdx.x;
    for (int i = tid; i < 16 * 256; i += 256) {
        int r = i >> 8, n = i & 255;
        kT[r * 257 + n] = ks[base + (size_t)r * NP + n];
        vT[r * 257 + n] = vs[base + (size_t)r * NP + n];
    }
    __syncthreads();
    int dd = tid >> 4, de = tid & 15;
    const float* kr = &kT[dd * 257];
    const float* vr = &vT[de * 257];
    float acc = 0.f;
#pragma unroll 8
    for (int n = 0; n < 256; n++) acc += kr[n] * vr[n];
    ktv[(size_t)tbh * 256 + dd * 16 + de] = acc;
}

// ---------------- attn out: o[t,b,h*16+dp,n] = 0.25 * sum_d q[t,b,h*16+d,n] * KtV[d][dp] ----
__global__ void attn_o_kernel(const float* __restrict__ qs, const float* __restrict__ ktv,
                              float* __restrict__ o)
{
    __shared__ float sK[256];
    int tbh = blockIdx.x;
    int hh = tbh & 15;
    int tb = tbh >> 4;
    int tid = threadIdx.x;        // n
    sK[tid] = ktv[(size_t)tbh * 256 + tid];
    __syncthreads();
    size_t base = ((size_t)tb * CCh + hh * 16) * NP + tid;
    float q[16];
#pragma unroll
    for (int d = 0; d < 16; d++) q[d] = qs[base + (size_t)d * NP];
#pragma unroll
    for (int dp = 0; dp < 16; dp++) {
        float acc = 0.f;
#pragma unroll
        for (int d = 0; d < 16; d++) acc += q[d] * sK[d * 16 + dp];
        o[base + (size_t)dp * NP] = acc * 0.25f;
    }
}

// ---------------- orchestration ----------------
extern "C" void kernel_launch(void* const* d_in, const int* in_sizes, int n_in,
                              void* d_out, int out_size)
{
    (void)in_sizes; (void)n_in; (void)out_size;
    const float* x        = (const float*)d_in[0];
    const float* q_w      = (const float*)d_in[1];
    const float* q_bn     = (const float*)d_in[2];
    const float* k_w      = (const float*)d_in[3];
    const float* k_bn     = (const float*)d_in[4];
    const float* v_w      = (const float*)d_in[5];
    const float* v_bn     = (const float*)d_in[6];
    const float* proj_w   = (const float*)d_in[7];
    const float* proj_bn  = (const float*)d_in[8];
    const float* tim_up_w = (const float*)d_in[9];
    const float* tim_bn1  = (const float*)d_in[10];
    const float* tim_dn_w = (const float*)d_in[11];
    const float* tim_bn2  = (const float*)d_in[12];
    const float* fc1_w    = (const float*)d_in[13];
    const float* fc1_b    = (const float*)d_in[14];
    const float* fc1_bn   = (const float*)d_in[15];
    const float* fc2_w    = (const float*)d_in[16];
    const float* fc2_b    = (const float*)d_in[17];
    const float* fc2_bn   = (const float*)d_in[18];
    float* outp = (float*)d_out;

    float *bufA, *bufB, *ybuf, *qs, *ks, *vs, *obuf, *hbuf, *ktv;
    float *scal, *shif, *t1s, *t1h, *t2s, *t2h;
    cudaGetSymbolAddress((void**)&bufA, g_bufA);
    cudaGetSymbolAddress((void**)&bufB, g_bufB);
    cudaGetSymbolAddress((void**)&ybuf, g_y);
    cudaGetSymbolAddress((void**)&qs,   g_qs);
    cudaGetSymbolAddress((void**)&ks,   g_ks);
    cudaGetSymbolAddress((void**)&vs,   g_vs);
    cudaGetSymbolAddress((void**)&obuf, g_o);
    cudaGetSymbolAddress((void**)&hbuf, g_h);
    cudaGetSymbolAddress((void**)&ktv,  g_ktv);
    cudaGetSymbolAddress((void**)&scal, g_scale);
    cudaGetSymbolAddress((void**)&shif, g_shift);
    cudaGetSymbolAddress((void**)&t1s,  g_t1s);
    cudaGetSymbolAddress((void**)&t1h,  g_t1h);
    cudaGetSymbolAddress((void**)&t2s,  g_t2s);
    cudaGetSymbolAddress((void**)&t2h,  g_t2h);

    cudaFuncSetAttribute(tim_conv1_kernel, cudaFuncAttributeMaxDynamicSharedMemorySize, CONV1_SMEM);

    // TIM BN folds (shared by the three branches)
    prep_bn_kernel<<<1, 256>>>(tim_bn1, nullptr, t1s, t1h, TRR);
    prep_bn_kernel<<<1, 256>>>(tim_bn2, nullptr, t2s, t2h, TT);

    const float* bw[3]  = {q_w, k_w, v_w};
    const float* bbn[3] = {q_bn, k_bn, v_bn};
    float* bout[3]      = {qs, ks, vs};

    for (int br = 0; br < 3; br++) {
        prep_bn_kernel<<<1, 256>>>(bbn[br], nullptr, scal, shif, CCh);
        gemm_bn_kernel<<<dim3(4, 4, TT*BBs), 256>>>(x, bw[br], ybuf, CCh, CCh, scal, shif);
        tim_conv1_kernel<<<dim3(CCh, BBs), 256, CONV1_SMEM>>>(ybuf, tim_up_w, t1s, t1h, bufA);
        lif_kernel<<<(4*BCN + 255)/256, 256>>>(bufA, bufB, 4*BCN, 4*BCN, 1.0f);
        tim_conv2_kernel<<<dim3(CCh, TT, BBs), 256>>>(bufB, tim_dn_w, t2s, t2h, ybuf);
        lif_kernel<<<(BCN + 255)/256, 256>>>(ybuf, bout[br], BCN, BCN, 1.0f);
    }

    // attention (linear, binary, exact)
    ktv_kernel<<<TT*BBs*16, 256>>>(ks, vs, ktv);
    attn_o_kernel<<<TT*BBs*16, 256>>>(qs, ktv, obuf);
    lif_kernel<<<(BCN + 255)/256, 256>>>(obuf, obuf, BCN, BCN, 0.5f);   // attn_lif vth=0.5

    // projection + BN + lif; residual h = x + spikes
    prep_bn_kernel<<<1, 256>>>(proj_bn, nullptr, scal, shif, CCh);
    gemm_bn_kernel<<<dim3(4, 4, TT*BBs), 256>>>(obuf, proj_w, ybuf, CCh, CCh, scal, shif);
    lif_resid_kernel<<<(BCN + 255)/256, 256>>>(ybuf, x, hbuf, BCN, BCN, 1.0f);

    // MLP
    prep_bn_kernel<<<(HIDD + 255)/256, 256>>>(fc1_bn, fc1_b, scal, shif, HIDD);
    gemm_bn_kernel<<<dim3(4, 16, TT*BBs), 256>>>(hbuf, fc1_w, bufA, HIDD, CCh, scal, shif);
    lif_kernel<<<(BHN + 255)/256, 256>>>(bufA, bufB, BHN, BHN, 1.0f);

    prep_bn_kernel<<<1, 256>>>(fc2_bn, fc2_b, scal, shif, CCh);
    gemm_bn_kernel<<<dim3(4, 4, TT*BBs), 256>>>(bufB, fc2_w, ybuf, CCh, HIDD, scal, shif);
    lif_resid_kernel<<<(BCN + 255)/256, 256>>>(ybuf, hbuf, outp, BCN, BCN, 1.0f);
}